// round 4
// baseline (speedup 1.0000x reference)
#include <cuda_runtime.h>
#include <cuda_fp16.h>
#include <cstdint>

// Problem constants
#define TOKENS   4096
#define IN_F     4096
#define OUT_F    11008
#define QGROUPS  64
#define KWORDS   (IN_F / 8)       // 512 packed int32 per output row

// GEMM tiling (Ampere-style mma.sync path: sm_103 base target, no tcgen05)
#define BM       128
#define BN       256
#define BK       64               // fp16 elements per stage along K (128B rows)
#define NSTAGE   3
#define NKIT     (IN_F / BK)      // 64
#define NTHREADS 256
#define A_STAGE_BYTES (BM * BK * 2)               // 16384
#define B_STAGE_BYTES (BN * BK * 2)               // 32768
#define STAGE_BYTES   (A_STAGE_BYTES + B_STAGE_BYTES)  // 49152
#define SMEM_TOTAL    (NSTAGE * STAGE_BYTES)      // 147456

// Scratch (device globals: allocation-free rule)
__device__ __half g_Bh[(size_t)OUT_F * IN_F];   // dequantized fp16 weights
__device__ __half g_Xh[(size_t)TOKENS * IN_F];  // fp16 activations

// ---------------------------------------------------------------------------
// Helpers
// ---------------------------------------------------------------------------
__device__ __forceinline__ uint32_t smem_u32(const void* p) {
    uint32_t a;
    asm("{ .reg .u64 t; cvta.to.shared.u64 t, %1; cvt.u32.u64 %0, t; }"
        : "=r"(a) : "l"(p));
    return a;
}

__device__ __forceinline__ void ldsm_x4(uint32_t addr, uint32_t* r) {
    asm volatile("ldmatrix.sync.aligned.m8n8.x4.shared.b16 {%0,%1,%2,%3}, [%4];"
                 : "=r"(r[0]), "=r"(r[1]), "=r"(r[2]), "=r"(r[3]) : "r"(addr));
}

__device__ __forceinline__ void mma16816(float* c, const uint32_t* a,
                                         uint32_t b0, uint32_t b1) {
    asm volatile(
        "mma.sync.aligned.m16n8k16.row.col.f32.f16.f16.f32 "
        "{%0,%1,%2,%3}, {%4,%5,%6,%7}, {%8,%9}, {%0,%1,%2,%3};"
        : "+f"(c[0]), "+f"(c[1]), "+f"(c[2]), "+f"(c[3])
        : "r"(a[0]), "r"(a[1]), "r"(a[2]), "r"(a[3]), "r"(b0), "r"(b1));
}

// ---------------------------------------------------------------------------
// Pre-kernel 1: convert activations to fp16 (round-to-nearest).
// fp16 mantissa step = 2^-11, same as tf32 -> output rel_err ~4e-4 < 1e-3.
// ---------------------------------------------------------------------------
__global__ void conv_x_kernel(const float4* __restrict__ x, int n8) {
    int i = blockIdx.x * blockDim.x + threadIdx.x;
    if (i >= n8) return;
    float4 a = x[2 * i];
    float4 b = x[2 * i + 1];
    __half2 h0 = __floats2half2_rn(a.x, a.y);
    __half2 h1 = __floats2half2_rn(a.z, a.w);
    __half2 h2 = __floats2half2_rn(b.x, b.y);
    __half2 h3 = __floats2half2_rn(b.z, b.w);
    uint4 o;
    o.x = *reinterpret_cast<uint32_t*>(&h0);
    o.y = *reinterpret_cast<uint32_t*>(&h1);
    o.z = *reinterpret_cast<uint32_t*>(&h2);
    o.w = *reinterpret_cast<uint32_t*>(&h3);
    reinterpret_cast<uint4*>(g_Xh)[i] = o;
}

// ---------------------------------------------------------------------------
// Pre-kernel 2: dequantize int4 -> fp16.
// One thread per packed int32 word (8 consecutive K in the same group).
// w[o,k] = scales[o,g] * (nibble - zp[o,g]),  g = k / 64. |w| <= 0.15, safe.
// ---------------------------------------------------------------------------
__global__ void dequant_kernel(const uint32_t* __restrict__ qw,
                               const uint32_t* __restrict__ qz,
                               const float* __restrict__ sc) {
    int idx = blockIdx.x * blockDim.x + threadIdx.x;
    if (idx >= OUT_F * KWORDS) return;
    int o  = idx >> 9;              // / 512
    int kw = idx & (KWORDS - 1);
    int g  = kw >> 3;               // group index (8 words per 64-elem group)
    float s = sc[o * QGROUPS + g];
    uint32_t zw = qz[o * (QGROUPS / 8) + (g >> 3)];
    float zp = (float)((zw >> ((g & 7) * 4)) & 0xF);
    float c  = -s * zp;             // w = s*v + c
    uint32_t w = qw[idx];
    __half2 h0 = __floats2half2_rn(fmaf(s, (float)((w      ) & 0xF), c),
                                   fmaf(s, (float)((w >>  4) & 0xF), c));
    __half2 h1 = __floats2half2_rn(fmaf(s, (float)((w >>  8) & 0xF), c),
                                   fmaf(s, (float)((w >> 12) & 0xF), c));
    __half2 h2 = __floats2half2_rn(fmaf(s, (float)((w >> 16) & 0xF), c),
                                   fmaf(s, (float)((w >> 20) & 0xF), c));
    __half2 h3 = __floats2half2_rn(fmaf(s, (float)((w >> 24) & 0xF), c),
                                   fmaf(s, (float)((w >> 28) & 0xF), c));
    uint4 o4;
    o4.x = *reinterpret_cast<uint32_t*>(&h0);
    o4.y = *reinterpret_cast<uint32_t*>(&h1);
    o4.z = *reinterpret_cast<uint32_t*>(&h2);
    o4.w = *reinterpret_cast<uint32_t*>(&h3);
    reinterpret_cast<uint4*>(g_Bh + (size_t)o * IN_F)[kw] = o4;
}

// ---------------------------------------------------------------------------
// Main GEMM: mma.sync.m16n8k16 fp16 -> f32, CTA 128x256x64, 3-stage cp.async.
// 8 warps in 2(M) x 4(N) grid; warp tile 64x64 (32 mma per K16 step).
// Smem: K-major 128B rows, SW128 swizzle -> conflict-free ldmatrix.
// ---------------------------------------------------------------------------
__global__ void __launch_bounds__(NTHREADS, 1)
gemm_f16_kernel(const float* __restrict__ bias, float* __restrict__ out) {
    extern __shared__ __align__(1024) char smem[];
    const uint32_t sbase = smem_u32(smem);
    const int tid  = threadIdx.x;
    const int wid  = tid >> 5;
    const int lane = tid & 31;
    const int wm   = wid & 1;        // warp M coord (2)
    const int wn   = wid >> 1;       // warp N coord (4)

    // M-fastest CTA order: concurrent CTAs share each B band via L2.
    const int mt = blockIdx.x & 31;  // 32 M tiles
    const int nt = blockIdx.x >> 5;  // 43 N tiles
    const int m0 = mt * BM;
    const int n0 = nt * BN;

    const __half* Abase = g_Xh + (size_t)m0 * IN_F;
    const __half* Bbase = g_Bh + (size_t)n0 * IN_F;

    // Stage loader: A 1024 chunks of 16B (4/thread), B 2048 chunks (8/thread).
    auto load_stage = [&](int s, int kl) {
        const int k0 = kl * BK;
        const uint32_t abuf = sbase + s * STAGE_BYTES;
        const uint32_t bbuf = abuf + A_STAGE_BYTES;
        const __half* Ag = Abase + k0;
        const __half* Bg = Bbase + k0;
        #pragma unroll
        for (int j = 0; j < 4; j++) {
            int q = tid + j * NTHREADS;       // 0..1023
            int r = q >> 3;                   // A row 0..127
            int c = q & 7;                    // 16B chunk 0..7
            uint32_t off = (uint32_t)(r * 128 + c * 16);
            uint32_t sw  = off ^ ((off >> 3) & 0x70);
            asm volatile("cp.async.cg.shared.global [%0], [%1], 16;"
                         :: "r"(abuf + sw), "l"(Ag + (size_t)r * IN_F + c * 8)
                         : "memory");
        }
        #pragma unroll
        for (int j = 0; j < 8; j++) {
            int q = tid + j * NTHREADS;       // 0..2047
            int r = q >> 3;                   // B row 0..255
            int c = q & 7;
            uint32_t off = (uint32_t)(r * 128 + c * 16);
            uint32_t sw  = off ^ ((off >> 3) & 0x70);
            asm volatile("cp.async.cg.shared.global [%0], [%1], 16;"
                         :: "r"(bbuf + sw), "l"(Bg + (size_t)r * IN_F + c * 8)
                         : "memory");
        }
    };

    // Prologue: fill NSTAGE-1 stages
    #pragma unroll
    for (int kl = 0; kl < NSTAGE - 1; kl++) {
        load_stage(kl, kl);
        asm volatile("cp.async.commit_group;" ::: "memory");
    }

    float acc[4][8][4];
    #pragma unroll
    for (int mi = 0; mi < 4; mi++)
        #pragma unroll
        for (int nf = 0; nf < 8; nf++)
            #pragma unroll
            for (int e = 0; e < 4; e++) acc[mi][nf][e] = 0.0f;

    const int lrow   = lane & 15;    // ldmatrix source row within 16
    const int lchunk = lane >> 4;    // 0: k0-7 chunk, 1: k8-15 chunk

    for (int kt = 0; kt < NKIT; kt++) {
        asm volatile("cp.async.wait_group %0;" :: "n"(NSTAGE - 2) : "memory");
        __syncthreads();

        // Prefetch stage kt+NSTAGE-1 (safe: all warps passed barrier above,
        // so nobody is still reading that buffer from iteration kt-1).
        const int kl = kt + NSTAGE - 1;
        if (kl < NKIT) load_stage(kl % NSTAGE, kl);
        asm volatile("cp.async.commit_group;" ::: "memory");

        // Compute on stage s
        const int s = kt % NSTAGE;
        const uint32_t abuf = sbase + s * STAGE_BYTES;
        const uint32_t bbuf = abuf + A_STAGE_BYTES;

        #pragma unroll
        for (int k16 = 0; k16 < BK / 16; k16++) {
            uint32_t af[4][4], bf[4][4];
            const int chunk = k16 * 2 + lchunk;
            #pragma unroll
            for (int mi = 0; mi < 4; mi++) {
                int row = wm * 64 + mi * 16 + lrow;
                uint32_t off = (uint32_t)(row * 128 + chunk * 16);
                ldsm_x4(abuf + (off ^ ((off >> 3) & 0x70)), af[mi]);
            }
            #pragma unroll
            for (int nj = 0; nj < 4; nj++) {
                int row = wn * 64 + nj * 16 + lrow;
                uint32_t off = (uint32_t)(row * 128 + chunk * 16);
                ldsm_x4(bbuf + (off ^ ((off >> 3) & 0x70)), bf[nj]);
            }
            #pragma unroll
            for (int mi = 0; mi < 4; mi++)
                #pragma unroll
                for (int nj = 0; nj < 4; nj++) {
                    // frag n = nj*16+0..7 : regs {b0(k0-7)=bf[0], b1(k8-15)=bf[2]}
                    mma16816(acc[mi][2 * nj],     af[mi], bf[nj][0], bf[nj][2]);
                    // frag n = nj*16+8..15: regs {bf[1], bf[3]}
                    mma16816(acc[mi][2 * nj + 1], af[mi], bf[nj][1], bf[nj][3]);
                }
        }
    }

    // Epilogue: fragment layout c0,c1 -> (row=q, col=2c..2c+1), c2,c3 -> row+8.
    const int qrow = lane >> 2;          // 0..7
    const int qcol = (lane & 3) * 2;
    float2 bv[8];
    #pragma unroll
    for (int nf = 0; nf < 8; nf++) {
        int c = n0 + wn * 64 + nf * 8 + qcol;
        bv[nf].x = __ldg(bias + c);
        bv[nf].y = __ldg(bias + c + 1);
    }
    #pragma unroll
    for (int mi = 0; mi < 4; mi++) {
        int gr = m0 + wm * 64 + mi * 16 + qrow;
        float* p0 = out + (size_t)gr * OUT_F;
        float* p1 = p0 + 8 * OUT_F;
        #pragma unroll
        for (int nf = 0; nf < 8; nf++) {
            int c = n0 + wn * 64 + nf * 8 + qcol;
            float2 v0, v1;
            v0.x = acc[mi][nf][0] + bv[nf].x;
            v0.y = acc[mi][nf][1] + bv[nf].y;
            v1.x = acc[mi][nf][2] + bv[nf].x;
            v1.y = acc[mi][nf][3] + bv[nf].y;
            *reinterpret_cast<float2*>(p0 + c) = v0;
            *reinterpret_cast<float2*>(p1 + c) = v1;
        }
    }
}

// ---------------------------------------------------------------------------
extern "C" void kernel_launch(void* const* d_in, const int* in_sizes, int n_in,
                              void* d_out, int out_size) {
    const float*    x    = (const float*)   d_in[0];
    const uint32_t* qw   = (const uint32_t*)d_in[1];
    const uint32_t* qz   = (const uint32_t*)d_in[2];
    const float*    sc   = (const float*)   d_in[3];
    const float*    bias = (const float*)   d_in[4];
    float*          out  = (float*)d_out;

    // 1) x -> fp16
    {
        int n8 = TOKENS * IN_F / 8;
        conv_x_kernel<<<(n8 + 255) / 256, 256>>>((const float4*)x, n8);
    }
    // 2) dequantize weights -> fp16 (once, hoisted out of the GEMM mainloop)
    {
        int n = OUT_F * KWORDS;
        dequant_kernel<<<(n + 255) / 256, 256>>>(qw, qz, sc);
    }
    // 3) fp16 mma.sync GEMM
    cudaFuncSetAttribute(gemm_f16_kernel,
                         cudaFuncAttributeMaxDynamicSharedMemorySize, SMEM_TOTAL);
    dim3 grid((TOKENS / BM) * (OUT_F / BN));  // 32 * 43 = 1376, M-fastest
    gemm_f16_kernel<<<grid, NTHREADS, SMEM_TOTAL>>>(bias, out);
}

// round 5
// speedup vs baseline: 1.0135x; 1.0135x over previous
#include <cuda_runtime.h>
#include <cuda_fp16.h>
#include <cstdint>

// Problem constants
#define TOKENS   4096
#define IN_F     4096
#define OUT_F    11008
#define QGROUPS  64
#define KWORDS   (IN_F / 8)       // 512 packed int32 per output row

// GEMM tiling (Ampere-style mma.sync path: sm_103 base target, no tcgen05)
#define BM       128
#define BN       256
#define BK       64               // fp16 elements per stage along K (128B rows)
#define NSTAGE   4
#define NKIT     (IN_F / BK)      // 64
#define NTHREADS 256
#define A_STAGE_BYTES (BM * BK * 2)               // 16384
#define B_STAGE_BYTES (BN * BK * 2)               // 32768
#define STAGE_BYTES   (A_STAGE_BYTES + B_STAGE_BYTES)  // 49152
#define SMEM_TOTAL    (NSTAGE * STAGE_BYTES)      // 196608

// Scratch (device globals: allocation-free rule)
__device__ __half g_Bh[(size_t)OUT_F * IN_F];   // dequantized fp16 weights
__device__ __half g_Xh[(size_t)TOKENS * IN_F];  // fp16 activations

// ---------------------------------------------------------------------------
// Helpers
// ---------------------------------------------------------------------------
__device__ __forceinline__ uint32_t smem_u32(const void* p) {
    uint32_t a;
    asm("{ .reg .u64 t; cvta.to.shared.u64 t, %1; cvt.u32.u64 %0, t; }"
        : "=r"(a) : "l"(p));
    return a;
}

__device__ __forceinline__ void ldsm_x4(uint32_t addr, uint32_t* r) {
    asm volatile("ldmatrix.sync.aligned.m8n8.x4.shared.b16 {%0,%1,%2,%3}, [%4];"
                 : "=r"(r[0]), "=r"(r[1]), "=r"(r[2]), "=r"(r[3]) : "r"(addr));
}

__device__ __forceinline__ void mma16816(float* c, const uint32_t* a,
                                         uint32_t b0, uint32_t b1) {
    asm volatile(
        "mma.sync.aligned.m16n8k16.row.col.f32.f16.f16.f32 "
        "{%0,%1,%2,%3}, {%4,%5,%6,%7}, {%8,%9}, {%0,%1,%2,%3};"
        : "+f"(c[0]), "+f"(c[1]), "+f"(c[2]), "+f"(c[3])
        : "r"(a[0]), "r"(a[1]), "r"(a[2]), "r"(a[3]), "r"(b0), "r"(b1));
}

// ---------------------------------------------------------------------------
// Pre-kernel 1: convert activations to fp16 (round-to-nearest).
// fp16 mantissa step = 2^-11, same as tf32 -> output rel_err ~4e-4 < 1e-3.
// ---------------------------------------------------------------------------
__global__ void conv_x_kernel(const float4* __restrict__ x, int n8) {
    int i = blockIdx.x * blockDim.x + threadIdx.x;
    if (i >= n8) return;
    float4 a = x[2 * i];
    float4 b = x[2 * i + 1];
    __half2 h0 = __floats2half2_rn(a.x, a.y);
    __half2 h1 = __floats2half2_rn(a.z, a.w);
    __half2 h2 = __floats2half2_rn(b.x, b.y);
    __half2 h3 = __floats2half2_rn(b.z, b.w);
    uint4 o;
    o.x = *reinterpret_cast<uint32_t*>(&h0);
    o.y = *reinterpret_cast<uint32_t*>(&h1);
    o.z = *reinterpret_cast<uint32_t*>(&h2);
    o.w = *reinterpret_cast<uint32_t*>(&h3);
    reinterpret_cast<uint4*>(g_Xh)[i] = o;
}

// ---------------------------------------------------------------------------
// Pre-kernel 2: dequantize int4 -> fp16.
// One thread per packed int32 word (8 consecutive K in the same group).
// w[o,k] = scales[o,g] * (nibble - zp[o,g]),  g = k / 64. |w| <= 0.15, safe.
// ---------------------------------------------------------------------------
__global__ void dequant_kernel(const uint32_t* __restrict__ qw,
                               const uint32_t* __restrict__ qz,
                               const float* __restrict__ sc) {
    int idx = blockIdx.x * blockDim.x + threadIdx.x;
    if (idx >= OUT_F * KWORDS) return;
    int o  = idx >> 9;              // / 512
    int kw = idx & (KWORDS - 1);
    int g  = kw >> 3;               // group index (8 words per 64-elem group)
    float s = sc[o * QGROUPS + g];
    uint32_t zw = qz[o * (QGROUPS / 8) + (g >> 3)];
    float zp = (float)((zw >> ((g & 7) * 4)) & 0xF);
    float c  = -s * zp;             // w = s*v + c
    uint32_t w = qw[idx];
    __half2 h0 = __floats2half2_rn(fmaf(s, (float)((w      ) & 0xF), c),
                                   fmaf(s, (float)((w >>  4) & 0xF), c));
    __half2 h1 = __floats2half2_rn(fmaf(s, (float)((w >>  8) & 0xF), c),
                                   fmaf(s, (float)((w >> 12) & 0xF), c));
    __half2 h2 = __floats2half2_rn(fmaf(s, (float)((w >> 16) & 0xF), c),
                                   fmaf(s, (float)((w >> 20) & 0xF), c));
    __half2 h3 = __floats2half2_rn(fmaf(s, (float)((w >> 24) & 0xF), c),
                                   fmaf(s, (float)((w >> 28) & 0xF), c));
    uint4 o4;
    o4.x = *reinterpret_cast<uint32_t*>(&h0);
    o4.y = *reinterpret_cast<uint32_t*>(&h1);
    o4.z = *reinterpret_cast<uint32_t*>(&h2);
    o4.w = *reinterpret_cast<uint32_t*>(&h3);
    reinterpret_cast<uint4*>(g_Bh + (size_t)o * IN_F)[kw] = o4;
}

// ---------------------------------------------------------------------------
// Main GEMM: mma.sync.m16n8k16 fp16 -> f32, CTA 128x256x64, 4-stage cp.async.
// 8 warps in 2(M) x 4(N) grid; warp tile 64x64 (32 mma per K16 step).
// Smem: K-major 128B rows, SW128 swizzle -> conflict-free ldmatrix.
// Register double-buffered fragments: LDS for step k+1 overlaps mma of step k.
// ---------------------------------------------------------------------------
__global__ void __launch_bounds__(NTHREADS, 1)
gemm_f16_kernel(const float* __restrict__ bias, float* __restrict__ out) {
    extern __shared__ __align__(1024) char smem[];
    const uint32_t sbase = smem_u32(smem);
    const int tid  = threadIdx.x;
    const int wid  = tid >> 5;
    const int lane = tid & 31;
    const int wm   = wid & 1;        // warp M coord (2)
    const int wn   = wid >> 1;       // warp N coord (4)

    // M-fastest CTA order: concurrent CTAs share each B band via L2.
    const int mt = blockIdx.x & 31;  // 32 M tiles
    const int nt = blockIdx.x >> 5;  // 43 N tiles
    const int m0 = mt * BM;
    const int n0 = nt * BN;

    const __half* Abase = g_Xh + (size_t)m0 * IN_F;
    const __half* Bbase = g_Bh + (size_t)n0 * IN_F;

    // Stage loader: A 1024 chunks of 16B (4/thread), B 2048 chunks (8/thread).
    auto load_stage = [&](int s, int kl) {
        const int k0 = kl * BK;
        const uint32_t abuf = sbase + s * STAGE_BYTES;
        const uint32_t bbuf = abuf + A_STAGE_BYTES;
        const __half* Ag = Abase + k0;
        const __half* Bg = Bbase + k0;
        #pragma unroll
        for (int j = 0; j < 4; j++) {
            int q = tid + j * NTHREADS;       // 0..1023
            int r = q >> 3;                   // A row 0..127
            int c = q & 7;                    // 16B chunk 0..7
            uint32_t off = (uint32_t)(r * 128 + c * 16);
            uint32_t sw  = off ^ ((off >> 3) & 0x70);
            asm volatile("cp.async.cg.shared.global [%0], [%1], 16;"
                         :: "r"(abuf + sw), "l"(Ag + (size_t)r * IN_F + c * 8)
                         : "memory");
        }
        #pragma unroll
        for (int j = 0; j < 8; j++) {
            int q = tid + j * NTHREADS;       // 0..2047
            int r = q >> 3;                   // B row 0..255
            int c = q & 7;
            uint32_t off = (uint32_t)(r * 128 + c * 16);
            uint32_t sw  = off ^ ((off >> 3) & 0x70);
            asm volatile("cp.async.cg.shared.global [%0], [%1], 16;"
                         :: "r"(bbuf + sw), "l"(Bg + (size_t)r * IN_F + c * 8)
                         : "memory");
        }
    };

    // Prologue: fill NSTAGE-1 stages
    #pragma unroll
    for (int kl = 0; kl < NSTAGE - 1; kl++) {
        load_stage(kl, kl);
        asm volatile("cp.async.commit_group;" ::: "memory");
    }

    float acc[4][8][4];
    #pragma unroll
    for (int mi = 0; mi < 4; mi++)
        #pragma unroll
        for (int nf = 0; nf < 8; nf++)
            #pragma unroll
            for (int e = 0; e < 4; e++) acc[mi][nf][e] = 0.0f;

    const int lrow   = lane & 15;    // ldmatrix source row within 16
    const int lchunk = lane >> 4;    // 0: k0-7 chunk, 1: k8-15 chunk

    // Per-warp swizzled fragment addresses: row depends only on lane, chunk
    // varies by k16 step. Precompute row-base offsets.
    uint32_t af[2][4][4], bf[2][4][4];

    auto load_frags = [&](uint32_t abuf, uint32_t bbuf, int k16, int buf) {
        const int chunk = k16 * 2 + lchunk;
        #pragma unroll
        for (int mi = 0; mi < 4; mi++) {
            int row = wm * 64 + mi * 16 + lrow;
            uint32_t off = (uint32_t)(row * 128 + chunk * 16);
            ldsm_x4(abuf + (off ^ ((off >> 3) & 0x70)), af[buf][mi]);
        }
        #pragma unroll
        for (int nj = 0; nj < 4; nj++) {
            int row = wn * 64 + nj * 16 + lrow;
            uint32_t off = (uint32_t)(row * 128 + chunk * 16);
            ldsm_x4(bbuf + (off ^ ((off >> 3) & 0x70)), bf[buf][nj]);
        }
    };

    for (int kt = 0; kt < NKIT; kt++) {
        asm volatile("cp.async.wait_group %0;" :: "n"(NSTAGE - 2) : "memory");
        __syncthreads();

        // Prefetch stage kt+NSTAGE-1 into buffer computed at kt-1 (all warps
        // passed the barrier above, so that buffer is no longer being read).
        const int kl = kt + NSTAGE - 1;
        if (kl < NKIT) load_stage(kl % NSTAGE, kl);
        asm volatile("cp.async.commit_group;" ::: "memory");

        // Compute on stage s with register double-buffered fragments.
        const int s = kt % NSTAGE;
        const uint32_t abuf = sbase + s * STAGE_BYTES;
        const uint32_t bbuf = abuf + A_STAGE_BYTES;

        load_frags(abuf, bbuf, 0, 0);
        #pragma unroll
        for (int k16 = 0; k16 < BK / 16; k16++) {
            const int cur = k16 & 1;
            if (k16 < BK / 16 - 1) load_frags(abuf, bbuf, k16 + 1, cur ^ 1);
            #pragma unroll
            for (int mi = 0; mi < 4; mi++)
                #pragma unroll
                for (int nj = 0; nj < 4; nj++) {
                    mma16816(acc[mi][2 * nj],     af[cur][mi],
                             bf[cur][nj][0], bf[cur][nj][2]);
                    mma16816(acc[mi][2 * nj + 1], af[cur][mi],
                             bf[cur][nj][1], bf[cur][nj][3]);
                }
        }
    }

    // Epilogue: fragment layout c0,c1 -> (row=q, col=2c..2c+1), c2,c3 -> row+8.
    const int qrow = lane >> 2;          // 0..7
    const int qcol = (lane & 3) * 2;
    float2 bv[8];
    #pragma unroll
    for (int nf = 0; nf < 8; nf++) {
        int c = n0 + wn * 64 + nf * 8 + qcol;
        bv[nf].x = __ldg(bias + c);
        bv[nf].y = __ldg(bias + c + 1);
    }
    #pragma unroll
    for (int mi = 0; mi < 4; mi++) {
        int gr = m0 + wm * 64 + mi * 16 + qrow;
        float* p0 = out + (size_t)gr * OUT_F;
        float* p1 = p0 + 8 * OUT_F;
        #pragma unroll
        for (int nf = 0; nf < 8; nf++) {
            int c = n0 + wn * 64 + nf * 8 + qcol;
            float2 v0, v1;
            v0.x = acc[mi][nf][0] + bv[nf].x;
            v0.y = acc[mi][nf][1] + bv[nf].y;
            v1.x = acc[mi][nf][2] + bv[nf].x;
            v1.y = acc[mi][nf][3] + bv[nf].y;
            *reinterpret_cast<float2*>(p0 + c) = v0;
            *reinterpret_cast<float2*>(p1 + c) = v1;
        }
    }
}

// ---------------------------------------------------------------------------
extern "C" void kernel_launch(void* const* d_in, const int* in_sizes, int n_in,
                              void* d_out, int out_size) {
    const float*    x    = (const float*)   d_in[0];
    const uint32_t* qw   = (const uint32_t*)d_in[1];
    const uint32_t* qz   = (const uint32_t*)d_in[2];
    const float*    sc   = (const float*)   d_in[3];
    const float*    bias = (const float*)   d_in[4];
    float*          out  = (float*)d_out;

    // 1) x -> fp16
    {
        int n8 = TOKENS * IN_F / 8;
        conv_x_kernel<<<(n8 + 255) / 256, 256>>>((const float4*)x, n8);
    }
    // 2) dequantize weights -> fp16 (once, hoisted out of the GEMM mainloop)
    {
        int n = OUT_F * KWORDS;
        dequant_kernel<<<(n + 255) / 256, 256>>>(qw, qz, sc);
    }
    // 3) fp16 mma.sync GEMM
    cudaFuncSetAttribute(gemm_f16_kernel,
                         cudaFuncAttributeMaxDynamicSharedMemorySize, SMEM_TOTAL);
    dim3 grid((TOKENS / BM) * (OUT_F / BN));  // 32 * 43 = 1376, M-fastest
    gemm_f16_kernel<<<grid, NTHREADS, SMEM_TOTAL>>>(bias, out);
}

// round 6
// speedup vs baseline: 1.1070x; 1.0923x over previous
#include <cuda_runtime.h>
#include <cuda_fp16.h>
#include <cstdint>

// Problem constants
#define TOKENS   4096
#define IN_F     4096
#define OUT_F    11008
#define QGROUPS  64
#define KWORDS   (IN_F / 8)       // 512 packed int32 per output row

// GEMM tiling: 2 CTAs/SM to fill barrier bubbles.
#define BM       128
#define BN       128
#define BK       64               // fp16 elements per stage along K (128B rows)
#define NSTAGE   3
#define NKIT     (IN_F / BK)      // 64
#define NTHREADS 128              // 4 warps, 2x2 grid of 64x64 warp tiles
#define A_STAGE_BYTES (BM * BK * 2)               // 16384
#define B_STAGE_BYTES (BN * BK * 2)               // 16384
#define STAGE_BYTES   (A_STAGE_BYTES + B_STAGE_BYTES)  // 32768
#define SMEM_TOTAL    (NSTAGE * STAGE_BYTES)      // 98304 (2 CTAs -> 192KB/SM)

// Scratch (device globals: allocation-free rule)
__device__ __half g_Bh[(size_t)OUT_F * IN_F];   // dequantized fp16 weights
__device__ __half g_Xh[(size_t)TOKENS * IN_F];  // fp16 activations

// ---------------------------------------------------------------------------
// Helpers
// ---------------------------------------------------------------------------
__device__ __forceinline__ uint32_t smem_u32(const void* p) {
    uint32_t a;
    asm("{ .reg .u64 t; cvta.to.shared.u64 t, %1; cvt.u32.u64 %0, t; }"
        : "=r"(a) : "l"(p));
    return a;
}

__device__ __forceinline__ void ldsm_x4(uint32_t addr, uint32_t* r) {
    asm volatile("ldmatrix.sync.aligned.m8n8.x4.shared.b16 {%0,%1,%2,%3}, [%4];"
                 : "=r"(r[0]), "=r"(r[1]), "=r"(r[2]), "=r"(r[3]) : "r"(addr));
}

__device__ __forceinline__ void mma16816(float* c, const uint32_t* a,
                                         uint32_t b0, uint32_t b1) {
    asm volatile(
        "mma.sync.aligned.m16n8k16.row.col.f32.f16.f16.f32 "
        "{%0,%1,%2,%3}, {%4,%5,%6,%7}, {%8,%9}, {%0,%1,%2,%3};"
        : "+f"(c[0]), "+f"(c[1]), "+f"(c[2]), "+f"(c[3])
        : "r"(a[0]), "r"(a[1]), "r"(a[2]), "r"(a[3]), "r"(b0), "r"(b1));
}

// ---------------------------------------------------------------------------
// Pre-kernel 1: convert activations to fp16 (round-to-nearest).
// fp16 mantissa step = 2^-11, same as tf32 -> output rel_err ~2.7e-4 < 1e-3.
// ---------------------------------------------------------------------------
__global__ void conv_x_kernel(const float4* __restrict__ x, int n8) {
    int i = blockIdx.x * blockDim.x + threadIdx.x;
    if (i >= n8) return;
    float4 a = x[2 * i];
    float4 b = x[2 * i + 1];
    __half2 h0 = __floats2half2_rn(a.x, a.y);
    __half2 h1 = __floats2half2_rn(a.z, a.w);
    __half2 h2 = __floats2half2_rn(b.x, b.y);
    __half2 h3 = __floats2half2_rn(b.z, b.w);
    uint4 o;
    o.x = *reinterpret_cast<uint32_t*>(&h0);
    o.y = *reinterpret_cast<uint32_t*>(&h1);
    o.z = *reinterpret_cast<uint32_t*>(&h2);
    o.w = *reinterpret_cast<uint32_t*>(&h3);
    reinterpret_cast<uint4*>(g_Xh)[i] = o;
}

// ---------------------------------------------------------------------------
// Pre-kernel 2: dequantize int4 -> fp16.
// w[o,k] = scales[o,g] * (nibble - zp[o,g]),  g = k / 64. |w| <= 0.15, safe.
// ---------------------------------------------------------------------------
__global__ void dequant_kernel(const uint32_t* __restrict__ qw,
                               const uint32_t* __restrict__ qz,
                               const float* __restrict__ sc) {
    int idx = blockIdx.x * blockDim.x + threadIdx.x;
    if (idx >= OUT_F * KWORDS) return;
    int o  = idx >> 9;              // / 512
    int kw = idx & (KWORDS - 1);
    int g  = kw >> 3;               // group index (8 words per 64-elem group)
    float s = sc[o * QGROUPS + g];
    uint32_t zw = qz[o * (QGROUPS / 8) + (g >> 3)];
    float zp = (float)((zw >> ((g & 7) * 4)) & 0xF);
    float c  = -s * zp;             // w = s*v + c
    uint32_t w = qw[idx];
    __half2 h0 = __floats2half2_rn(fmaf(s, (float)((w      ) & 0xF), c),
                                   fmaf(s, (float)((w >>  4) & 0xF), c));
    __half2 h1 = __floats2half2_rn(fmaf(s, (float)((w >>  8) & 0xF), c),
                                   fmaf(s, (float)((w >> 12) & 0xF), c));
    __half2 h2 = __floats2half2_rn(fmaf(s, (float)((w >> 16) & 0xF), c),
                                   fmaf(s, (float)((w >> 20) & 0xF), c));
    __half2 h3 = __floats2half2_rn(fmaf(s, (float)((w >> 24) & 0xF), c),
                                   fmaf(s, (float)((w >> 28) & 0xF), c));
    uint4 o4;
    o4.x = *reinterpret_cast<uint32_t*>(&h0);
    o4.y = *reinterpret_cast<uint32_t*>(&h1);
    o4.z = *reinterpret_cast<uint32_t*>(&h2);
    o4.w = *reinterpret_cast<uint32_t*>(&h3);
    reinterpret_cast<uint4*>(g_Bh + (size_t)o * IN_F)[kw] = o4;
}

// ---------------------------------------------------------------------------
// Main GEMM: mma.sync.m16n8k16 fp16 -> f32, CTA 128x128x64, 3-stage cp.async,
// 2 CTAs per SM (cross-CTA latency hiding across barrier bubbles).
// 4 warps in 2(M) x 2(N) grid; warp tile 64x64 (32 mma per K16 step).
// Smem: K-major 128B rows, SW128 swizzle -> conflict-free ldmatrix.
// ---------------------------------------------------------------------------
__global__ void __launch_bounds__(NTHREADS, 2)
gemm_f16_kernel(const float* __restrict__ bias, float* __restrict__ out) {
    extern __shared__ __align__(1024) char smem[];
    const uint32_t sbase = smem_u32(smem);
    const int tid  = threadIdx.x;
    const int wid  = tid >> 5;
    const int lane = tid & 31;
    const int wm   = wid & 1;        // warp M coord (2)
    const int wn   = wid >> 1;       // warp N coord (2)

    // M-fastest CTA order: concurrent CTAs share each B band via L2.
    const int mt = blockIdx.x & 31;  // 32 M tiles
    const int nt = blockIdx.x >> 5;  // 86 N tiles
    const int m0 = mt * BM;
    const int n0 = nt * BN;

    const __half* Abase = g_Xh + (size_t)m0 * IN_F;
    const __half* Bbase = g_Bh + (size_t)n0 * IN_F;

    // Stage loader: A 1024 chunks of 16B (8/thread), B 1024 chunks (8/thread).
    auto load_stage = [&](int s, int kl) {
        const int k0 = kl * BK;
        const uint32_t abuf = sbase + s * STAGE_BYTES;
        const uint32_t bbuf = abuf + A_STAGE_BYTES;
        const __half* Ag = Abase + k0;
        const __half* Bg = Bbase + k0;
        #pragma unroll
        for (int j = 0; j < 8; j++) {
            int q = tid + j * NTHREADS;       // 0..1023
            int r = q >> 3;                   // A row 0..127
            int c = q & 7;                    // 16B chunk 0..7
            uint32_t off = (uint32_t)(r * 128 + c * 16);
            uint32_t sw  = off ^ ((off >> 3) & 0x70);
            asm volatile("cp.async.cg.shared.global [%0], [%1], 16;"
                         :: "r"(abuf + sw), "l"(Ag + (size_t)r * IN_F + c * 8)
                         : "memory");
        }
        #pragma unroll
        for (int j = 0; j < 8; j++) {
            int q = tid + j * NTHREADS;       // 0..1023
            int r = q >> 3;                   // B row 0..127
            int c = q & 7;
            uint32_t off = (uint32_t)(r * 128 + c * 16);
            uint32_t sw  = off ^ ((off >> 3) & 0x70);
            asm volatile("cp.async.cg.shared.global [%0], [%1], 16;"
                         :: "r"(bbuf + sw), "l"(Bg + (size_t)r * IN_F + c * 8)
                         : "memory");
        }
    };

    // Prologue: fill NSTAGE-1 stages
    #pragma unroll
    for (int kl = 0; kl < NSTAGE - 1; kl++) {
        load_stage(kl, kl);
        asm volatile("cp.async.commit_group;" ::: "memory");
    }

    float acc[4][8][4];
    #pragma unroll
    for (int mi = 0; mi < 4; mi++)
        #pragma unroll
        for (int nf = 0; nf < 8; nf++)
            #pragma unroll
            for (int e = 0; e < 4; e++) acc[mi][nf][e] = 0.0f;

    const int lrow   = lane & 15;    // ldmatrix source row within 16
    const int lchunk = lane >> 4;    // 0: k0-7 chunk, 1: k8-15 chunk

    for (int kt = 0; kt < NKIT; kt++) {
        asm volatile("cp.async.wait_group %0;" :: "n"(NSTAGE - 2) : "memory");
        __syncthreads();

        // Prefetch stage kt+NSTAGE-1 (its buffer was consumed at kt-1; all
        // warps passed the barrier above, so it is free).
        const int kl = kt + NSTAGE - 1;
        if (kl < NKIT) load_stage(kl % NSTAGE, kl);
        asm volatile("cp.async.commit_group;" ::: "memory");

        // Compute on stage s.
        const int s = kt % NSTAGE;
        const uint32_t abuf = sbase + s * STAGE_BYTES;
        const uint32_t bbuf = abuf + A_STAGE_BYTES;

        #pragma unroll
        for (int k16 = 0; k16 < BK / 16; k16++) {
            uint32_t af[4][4], bf[4][4];
            const int chunk = k16 * 2 + lchunk;
            #pragma unroll
            for (int mi = 0; mi < 4; mi++) {
                int row = wm * 64 + mi * 16 + lrow;
                uint32_t off = (uint32_t)(row * 128 + chunk * 16);
                ldsm_x4(abuf + (off ^ ((off >> 3) & 0x70)), af[mi]);
            }
            #pragma unroll
            for (int nj = 0; nj < 4; nj++) {
                int row = wn * 64 + nj * 16 + lrow;
                uint32_t off = (uint32_t)(row * 128 + chunk * 16);
                ldsm_x4(bbuf + (off ^ ((off >> 3) & 0x70)), bf[nj]);
            }
            #pragma unroll
            for (int mi = 0; mi < 4; mi++)
                #pragma unroll
                for (int nj = 0; nj < 4; nj++) {
                    mma16816(acc[mi][2 * nj],     af[mi], bf[nj][0], bf[nj][2]);
                    mma16816(acc[mi][2 * nj + 1], af[mi], bf[nj][1], bf[nj][3]);
                }
        }
    }

    // Epilogue: fragment layout c0,c1 -> (row=q, col=2c..2c+1), c2,c3 -> row+8.
    const int qrow = lane >> 2;          // 0..7
    const int qcol = (lane & 3) * 2;
    float2 bv[8];
    #pragma unroll
    for (int nf = 0; nf < 8; nf++) {
        int c = n0 + wn * 64 + nf * 8 + qcol;
        bv[nf].x = __ldg(bias + c);
        bv[nf].y = __ldg(bias + c + 1);
    }
    #pragma unroll
    for (int mi = 0; mi < 4; mi++) {
        int gr = m0 + wm * 64 + mi * 16 + qrow;
        float* p0 = out + (size_t)gr * OUT_F;
        float* p1 = p0 + 8 * OUT_F;
        #pragma unroll
        for (int nf = 0; nf < 8; nf++) {
            int c = n0 + wn * 64 + nf * 8 + qcol;
            float2 v0, v1;
            v0.x = acc[mi][nf][0] + bv[nf].x;
            v0.y = acc[mi][nf][1] + bv[nf].y;
            v1.x = acc[mi][nf][2] + bv[nf].x;
            v1.y = acc[mi][nf][3] + bv[nf].y;
            *reinterpret_cast<float2*>(p0 + c) = v0;
            *reinterpret_cast<float2*>(p1 + c) = v1;
        }
    }
}

// ---------------------------------------------------------------------------
extern "C" void kernel_launch(void* const* d_in, const int* in_sizes, int n_in,
                              void* d_out, int out_size) {
    const float*    x    = (const float*)   d_in[0];
    const uint32_t* qw   = (const uint32_t*)d_in[1];
    const uint32_t* qz   = (const uint32_t*)d_in[2];
    const float*    sc   = (const float*)   d_in[3];
    const float*    bias = (const float*)   d_in[4];
    float*          out  = (float*)d_out;

    // 1) x -> fp16
    {
        int n8 = TOKENS * IN_F / 8;
        conv_x_kernel<<<(n8 + 255) / 256, 256>>>((const float4*)x, n8);
    }
    // 2) dequantize weights -> fp16 (once, hoisted out of the GEMM mainloop)
    {
        int n = OUT_F * KWORDS;
        dequant_kernel<<<(n + 255) / 256, 256>>>(qw, qz, sc);
    }
    // 3) fp16 mma.sync GEMM, 2 CTAs/SM
    cudaFuncSetAttribute(gemm_f16_kernel,
                         cudaFuncAttributeMaxDynamicSharedMemorySize, SMEM_TOTAL);
    dim3 grid((TOKENS / BM) * (OUT_F / BN));  // 32 * 86 = 2752, M-fastest
    gemm_f16_kernel<<<grid, NTHREADS, SMEM_TOTAL>>>(bias, out);
}

// round 7
// speedup vs baseline: 1.1084x; 1.0012x over previous
#include <cuda_runtime.h>
#include <cuda_fp16.h>
#include <cstdint>

// Problem constants
#define TOKENS   4096
#define IN_F     4096
#define OUT_F    11008
#define QGROUPS  64
#define KWORDS   (IN_F / 8)       // 512 packed int32 per output row

// GEMM tiling: 2 CTAs/SM + register-double-buffered fragments.
#define BM       128
#define BN       128
#define BK       64               // fp16 elements per stage along K (128B rows)
#define NSTAGE   3
#define NKIT     (IN_F / BK)      // 64
#define NTHREADS 128              // 4 warps, 2x2 grid of 64x64 warp tiles
#define A_STAGE_BYTES (BM * BK * 2)               // 16384
#define B_STAGE_BYTES (BN * BK * 2)               // 16384
#define STAGE_BYTES   (A_STAGE_BYTES + B_STAGE_BYTES)  // 32768
#define SMEM_TOTAL    (NSTAGE * STAGE_BYTES)      // 98304 (2 CTAs -> 192KB/SM)

// Scratch (device globals: allocation-free rule)
__device__ __half g_Bh[(size_t)OUT_F * IN_F];   // dequantized fp16 weights
__device__ __half g_Xh[(size_t)TOKENS * IN_F];  // fp16 activations

// ---------------------------------------------------------------------------
// Helpers
// ---------------------------------------------------------------------------
__device__ __forceinline__ uint32_t smem_u32(const void* p) {
    uint32_t a;
    asm("{ .reg .u64 t; cvta.to.shared.u64 t, %1; cvt.u32.u64 %0, t; }"
        : "=r"(a) : "l"(p));
    return a;
}

__device__ __forceinline__ void ldsm_x4(uint32_t addr, uint32_t* r) {
    asm volatile("ldmatrix.sync.aligned.m8n8.x4.shared.b16 {%0,%1,%2,%3}, [%4];"
                 : "=r"(r[0]), "=r"(r[1]), "=r"(r[2]), "=r"(r[3]) : "r"(addr));
}

__device__ __forceinline__ void mma16816(float* c, const uint32_t* a,
                                         uint32_t b0, uint32_t b1) {
    asm volatile(
        "mma.sync.aligned.m16n8k16.row.col.f32.f16.f16.f32 "
        "{%0,%1,%2,%3}, {%4,%5,%6,%7}, {%8,%9}, {%0,%1,%2,%3};"
        : "+f"(c[0]), "+f"(c[1]), "+f"(c[2]), "+f"(c[3])
        : "r"(a[0]), "r"(a[1]), "r"(a[2]), "r"(a[3]), "r"(b0), "r"(b1));
}

// ---------------------------------------------------------------------------
// Pre-kernel 1: convert activations to fp16 (round-to-nearest).
// fp16 mantissa step = 2^-11, same as tf32 -> output rel_err ~2.7e-4 < 1e-3.
// ---------------------------------------------------------------------------
__global__ void conv_x_kernel(const float4* __restrict__ x, int n8) {
    int i = blockIdx.x * blockDim.x + threadIdx.x;
    if (i >= n8) return;
    float4 a = x[2 * i];
    float4 b = x[2 * i + 1];
    __half2 h0 = __floats2half2_rn(a.x, a.y);
    __half2 h1 = __floats2half2_rn(a.z, a.w);
    __half2 h2 = __floats2half2_rn(b.x, b.y);
    __half2 h3 = __floats2half2_rn(b.z, b.w);
    uint4 o;
    o.x = *reinterpret_cast<uint32_t*>(&h0);
    o.y = *reinterpret_cast<uint32_t*>(&h1);
    o.z = *reinterpret_cast<uint32_t*>(&h2);
    o.w = *reinterpret_cast<uint32_t*>(&h3);
    reinterpret_cast<uint4*>(g_Xh)[i] = o;
}

// ---------------------------------------------------------------------------
// Pre-kernel 2: dequantize int4 -> fp16.
// w[o,k] = scales[o,g] * (nibble - zp[o,g]),  g = k / 64. |w| <= 0.15, safe.
// ---------------------------------------------------------------------------
__global__ void dequant_kernel(const uint32_t* __restrict__ qw,
                               const uint32_t* __restrict__ qz,
                               const float* __restrict__ sc) {
    int idx = blockIdx.x * blockDim.x + threadIdx.x;
    if (idx >= OUT_F * KWORDS) return;
    int o  = idx >> 9;              // / 512
    int kw = idx & (KWORDS - 1);
    int g  = kw >> 3;               // group index (8 words per 64-elem group)
    float s = sc[o * QGROUPS + g];
    uint32_t zw = qz[o * (QGROUPS / 8) + (g >> 3)];
    float zp = (float)((zw >> ((g & 7) * 4)) & 0xF);
    float c  = -s * zp;             // w = s*v + c
    uint32_t w = qw[idx];
    __half2 h0 = __floats2half2_rn(fmaf(s, (float)((w      ) & 0xF), c),
                                   fmaf(s, (float)((w >>  4) & 0xF), c));
    __half2 h1 = __floats2half2_rn(fmaf(s, (float)((w >>  8) & 0xF), c),
                                   fmaf(s, (float)((w >> 12) & 0xF), c));
    __half2 h2 = __floats2half2_rn(fmaf(s, (float)((w >> 16) & 0xF), c),
                                   fmaf(s, (float)((w >> 20) & 0xF), c));
    __half2 h3 = __floats2half2_rn(fmaf(s, (float)((w >> 24) & 0xF), c),
                                   fmaf(s, (float)((w >> 28) & 0xF), c));
    uint4 o4;
    o4.x = *reinterpret_cast<uint32_t*>(&h0);
    o4.y = *reinterpret_cast<uint32_t*>(&h1);
    o4.z = *reinterpret_cast<uint32_t*>(&h2);
    o4.w = *reinterpret_cast<uint32_t*>(&h3);
    reinterpret_cast<uint4*>(g_Bh + (size_t)o * IN_F)[kw] = o4;
}

// ---------------------------------------------------------------------------
// Main GEMM: mma.sync.m16n8k16 fp16 -> f32, CTA 128x128x64, 3-stage cp.async,
// 2 CTAs per SM (cross-CTA bubble filling) + register double-buffered
// fragments (LDSM burst of step k+1 overlaps the 32 HMMA of step k, so the
// two resident warps per SMSP don't collide in their crossbar phases).
// ---------------------------------------------------------------------------
__global__ void __launch_bounds__(NTHREADS, 2)
gemm_f16_kernel(const float* __restrict__ bias, float* __restrict__ out) {
    extern __shared__ __align__(1024) char smem[];
    const uint32_t sbase = smem_u32(smem);
    const int tid  = threadIdx.x;
    const int wid  = tid >> 5;
    const int lane = tid & 31;
    const int wm   = wid & 1;        // warp M coord (2)
    const int wn   = wid >> 1;       // warp N coord (2)

    // M-fastest CTA order: concurrent CTAs share each B band via L2.
    const int mt = blockIdx.x & 31;  // 32 M tiles
    const int nt = blockIdx.x >> 5;  // 86 N tiles
    const int m0 = mt * BM;
    const int n0 = nt * BN;

    const __half* Abase = g_Xh + (size_t)m0 * IN_F;
    const __half* Bbase = g_Bh + (size_t)n0 * IN_F;

    // Stage loader: A 1024 chunks of 16B (8/thread), B 1024 chunks (8/thread).
    auto load_stage = [&](int s, int kl) {
        const int k0 = kl * BK;
        const uint32_t abuf = sbase + s * STAGE_BYTES;
        const uint32_t bbuf = abuf + A_STAGE_BYTES;
        const __half* Ag = Abase + k0;
        const __half* Bg = Bbase + k0;
        #pragma unroll
        for (int j = 0; j < 8; j++) {
            int q = tid + j * NTHREADS;       // 0..1023
            int r = q >> 3;                   // A row 0..127
            int c = q & 7;                    // 16B chunk 0..7
            uint32_t off = (uint32_t)(r * 128 + c * 16);
            uint32_t sw  = off ^ ((off >> 3) & 0x70);
            asm volatile("cp.async.cg.shared.global [%0], [%1], 16;"
                         :: "r"(abuf + sw), "l"(Ag + (size_t)r * IN_F + c * 8)
                         : "memory");
        }
        #pragma unroll
        for (int j = 0; j < 8; j++) {
            int q = tid + j * NTHREADS;       // 0..1023
            int r = q >> 3;                   // B row 0..127
            int c = q & 7;
            uint32_t off = (uint32_t)(r * 128 + c * 16);
            uint32_t sw  = off ^ ((off >> 3) & 0x70);
            asm volatile("cp.async.cg.shared.global [%0], [%1], 16;"
                         :: "r"(bbuf + sw), "l"(Bg + (size_t)r * IN_F + c * 8)
                         : "memory");
        }
    };

    // Prologue: fill NSTAGE-1 stages
    #pragma unroll
    for (int kl = 0; kl < NSTAGE - 1; kl++) {
        load_stage(kl, kl);
        asm volatile("cp.async.commit_group;" ::: "memory");
    }

    float acc[4][8][4];
    #pragma unroll
    for (int mi = 0; mi < 4; mi++)
        #pragma unroll
        for (int nf = 0; nf < 8; nf++)
            #pragma unroll
            for (int e = 0; e < 4; e++) acc[mi][nf][e] = 0.0f;

    const int lrow   = lane & 15;    // ldmatrix source row within 16
    const int lchunk = lane >> 4;    // 0: k0-7 chunk, 1: k8-15 chunk

    uint32_t af[2][4][4], bf[2][4][4];

    auto load_frags = [&](uint32_t abuf, uint32_t bbuf, int k16, int buf) {
        const int chunk = k16 * 2 + lchunk;
        #pragma unroll
        for (int mi = 0; mi < 4; mi++) {
            int row = wm * 64 + mi * 16 + lrow;
            uint32_t off = (uint32_t)(row * 128 + chunk * 16);
            ldsm_x4(abuf + (off ^ ((off >> 3) & 0x70)), af[buf][mi]);
        }
        #pragma unroll
        for (int nj = 0; nj < 4; nj++) {
            int row = wn * 64 + nj * 16 + lrow;
            uint32_t off = (uint32_t)(row * 128 + chunk * 16);
            ldsm_x4(bbuf + (off ^ ((off >> 3) & 0x70)), bf[buf][nj]);
        }
    };

    for (int kt = 0; kt < NKIT; kt++) {
        asm volatile("cp.async.wait_group %0;" :: "n"(NSTAGE - 2) : "memory");
        __syncthreads();

        // Prefetch stage kt+NSTAGE-1 (its buffer was consumed at kt-1; all
        // warps passed the barrier above, so it is free).
        const int kl = kt + NSTAGE - 1;
        if (kl < NKIT) load_stage(kl % NSTAGE, kl);
        asm volatile("cp.async.commit_group;" ::: "memory");

        // Compute on stage s with register-double-buffered fragments.
        const int s = kt % NSTAGE;
        const uint32_t abuf = sbase + s * STAGE_BYTES;
        const uint32_t bbuf = abuf + A_STAGE_BYTES;

        load_frags(abuf, bbuf, 0, 0);
        #pragma unroll
        for (int k16 = 0; k16 < BK / 16; k16++) {
            const int cur = k16 & 1;
            if (k16 < BK / 16 - 1) load_frags(abuf, bbuf, k16 + 1, cur ^ 1);
            #pragma unroll
            for (int mi = 0; mi < 4; mi++)
                #pragma unroll
                for (int nj = 0; nj < 4; nj++) {
                    mma16816(acc[mi][2 * nj],     af[cur][mi],
                             bf[cur][nj][0], bf[cur][nj][2]);
                    mma16816(acc[mi][2 * nj + 1], af[cur][mi],
                             bf[cur][nj][1], bf[cur][nj][3]);
                }
        }
    }

    // Epilogue: fragment layout c0,c1 -> (row=q, col=2c..2c+1), c2,c3 -> row+8.
    const int qrow = lane >> 2;          // 0..7
    const int qcol = (lane & 3) * 2;
    float2 bv[8];
    #pragma unroll
    for (int nf = 0; nf < 8; nf++) {
        int c = n0 + wn * 64 + nf * 8 + qcol;
        bv[nf].x = __ldg(bias + c);
        bv[nf].y = __ldg(bias + c + 1);
    }
    #pragma unroll
    for (int mi = 0; mi < 4; mi++) {
        int gr = m0 + wm * 64 + mi * 16 + qrow;
        float* p0 = out + (size_t)gr * OUT_F;
        float* p1 = p0 + 8 * OUT_F;
        #pragma unroll
        for (int nf = 0; nf < 8; nf++) {
            int c = n0 + wn * 64 + nf * 8 + qcol;
            float2 v0, v1;
            v0.x = acc[mi][nf][0] + bv[nf].x;
            v0.y = acc[mi][nf][1] + bv[nf].y;
            v1.x = acc[mi][nf][2] + bv[nf].x;
            v1.y = acc[mi][nf][3] + bv[nf].y;
            *reinterpret_cast<float2*>(p0 + c) = v0;
            *reinterpret_cast<float2*>(p1 + c) = v1;
        }
    }
}

// ---------------------------------------------------------------------------
extern "C" void kernel_launch(void* const* d_in, const int* in_sizes, int n_in,
                              void* d_out, int out_size) {
    const float*    x    = (const float*)   d_in[0];
    const uint32_t* qw   = (const uint32_t*)d_in[1];
    const uint32_t* qz   = (const uint32_t*)d_in[2];
    const float*    sc   = (const float*)   d_in[3];
    const float*    bias = (const float*)   d_in[4];
    float*          out  = (float*)d_out;

    // 1) x -> fp16
    {
        int n8 = TOKENS * IN_F / 8;
        conv_x_kernel<<<(n8 + 255) / 256, 256>>>((const float4*)x, n8);
    }
    // 2) dequantize weights -> fp16 (once, hoisted out of the GEMM mainloop)
    {
        int n = OUT_F * KWORDS;
        dequant_kernel<<<(n + 255) / 256, 256>>>(qw, qz, sc);
    }
    // 3) fp16 mma.sync GEMM, 2 CTAs/SM + frag double buffering
    cudaFuncSetAttribute(gemm_f16_kernel,
                         cudaFuncAttributeMaxDynamicSharedMemorySize, SMEM_TOTAL);
    dim3 grid((TOKENS / BM) * (OUT_F / BN));  // 32 * 86 = 2752, M-fastest
    gemm_f16_kernel<<<grid, NTHREADS, SMEM_TOTAL>>>(bias, out);
}

// round 8
// speedup vs baseline: 1.1734x; 1.0587x over previous
#include <cuda_runtime.h>
#include <cuda_fp16.h>
#include <cstdint>

// Problem constants
#define TOKENS   4096
#define IN_F     4096
#define OUT_F    11008
#define QGROUPS  64
#define KWORDS   (IN_F / 8)       // 512 packed int32 per output row

// GEMM tiling: small tiles, 3 CTAs/SM (wave rounding + 3 warps/SMSP).
#define BM       64
#define BN       128
#define BK       64               // fp16 elements per stage along K (128B rows)
#define NSTAGE   3
#define NKIT     (IN_F / BK)      // 64
#define NTHREADS 128              // 4 warps, 2x2 grid of 32x64 warp tiles
#define A_STAGE_BYTES (BM * BK * 2)               // 8192
#define B_STAGE_BYTES (BN * BK * 2)               // 16384
#define STAGE_BYTES   (A_STAGE_BYTES + B_STAGE_BYTES)  // 24576
#define SMEM_TOTAL    (NSTAGE * STAGE_BYTES)      // 73728 (3 CTAs -> 216KB/SM)

// Scratch (device globals: allocation-free rule)
__device__ __half g_Bh[(size_t)OUT_F * IN_F];   // dequantized fp16 weights
__device__ __half g_Xh[(size_t)TOKENS * IN_F];  // fp16 activations

// ---------------------------------------------------------------------------
// Helpers
// ---------------------------------------------------------------------------
__device__ __forceinline__ uint32_t smem_u32(const void* p) {
    uint32_t a;
    asm("{ .reg .u64 t; cvta.to.shared.u64 t, %1; cvt.u32.u64 %0, t; }"
        : "=r"(a) : "l"(p));
    return a;
}

__device__ __forceinline__ void ldsm_x4(uint32_t addr, uint32_t* r) {
    asm volatile("ldmatrix.sync.aligned.m8n8.x4.shared.b16 {%0,%1,%2,%3}, [%4];"
                 : "=r"(r[0]), "=r"(r[1]), "=r"(r[2]), "=r"(r[3]) : "r"(addr));
}

__device__ __forceinline__ void mma16816(float* c, const uint32_t* a,
                                         uint32_t b0, uint32_t b1) {
    asm volatile(
        "mma.sync.aligned.m16n8k16.row.col.f32.f16.f16.f32 "
        "{%0,%1,%2,%3}, {%4,%5,%6,%7}, {%8,%9}, {%0,%1,%2,%3};"
        : "+f"(c[0]), "+f"(c[1]), "+f"(c[2]), "+f"(c[3])
        : "r"(a[0]), "r"(a[1]), "r"(a[2]), "r"(a[3]), "r"(b0), "r"(b1));
}

// ---------------------------------------------------------------------------
// Pre-kernel 1: convert activations to fp16 (round-to-nearest).
// fp16 mantissa step = 2^-11, same as tf32 -> output rel_err ~2.7e-4 < 1e-3.
// ---------------------------------------------------------------------------
__global__ void conv_x_kernel(const float4* __restrict__ x, int n8) {
    int i = blockIdx.x * blockDim.x + threadIdx.x;
    if (i >= n8) return;
    float4 a = x[2 * i];
    float4 b = x[2 * i + 1];
    __half2 h0 = __floats2half2_rn(a.x, a.y);
    __half2 h1 = __floats2half2_rn(a.z, a.w);
    __half2 h2 = __floats2half2_rn(b.x, b.y);
    __half2 h3 = __floats2half2_rn(b.z, b.w);
    uint4 o;
    o.x = *reinterpret_cast<uint32_t*>(&h0);
    o.y = *reinterpret_cast<uint32_t*>(&h1);
    o.z = *reinterpret_cast<uint32_t*>(&h2);
    o.w = *reinterpret_cast<uint32_t*>(&h3);
    reinterpret_cast<uint4*>(g_Xh)[i] = o;
}

// ---------------------------------------------------------------------------
// Pre-kernel 2: dequantize int4 -> fp16.
// w[o,k] = scales[o,g] * (nibble - zp[o,g]),  g = k / 64. |w| <= 0.15, safe.
// ---------------------------------------------------------------------------
__global__ void dequant_kernel(const uint32_t* __restrict__ qw,
                               const uint32_t* __restrict__ qz,
                               const float* __restrict__ sc) {
    int idx = blockIdx.x * blockDim.x + threadIdx.x;
    if (idx >= OUT_F * KWORDS) return;
    int o  = idx >> 9;              // / 512
    int kw = idx & (KWORDS - 1);
    int g  = kw >> 3;               // group index (8 words per 64-elem group)
    float s = sc[o * QGROUPS + g];
    uint32_t zw = qz[o * (QGROUPS / 8) + (g >> 3)];
    float zp = (float)((zw >> ((g & 7) * 4)) & 0xF);
    float c  = -s * zp;             // w = s*v + c
    uint32_t w = qw[idx];
    __half2 h0 = __floats2half2_rn(fmaf(s, (float)((w      ) & 0xF), c),
                                   fmaf(s, (float)((w >>  4) & 0xF), c));
    __half2 h1 = __floats2half2_rn(fmaf(s, (float)((w >>  8) & 0xF), c),
                                   fmaf(s, (float)((w >> 12) & 0xF), c));
    __half2 h2 = __floats2half2_rn(fmaf(s, (float)((w >> 16) & 0xF), c),
                                   fmaf(s, (float)((w >> 20) & 0xF), c));
    __half2 h3 = __floats2half2_rn(fmaf(s, (float)((w >> 24) & 0xF), c),
                                   fmaf(s, (float)((w >> 28) & 0xF), c));
    uint4 o4;
    o4.x = *reinterpret_cast<uint32_t*>(&h0);
    o4.y = *reinterpret_cast<uint32_t*>(&h1);
    o4.z = *reinterpret_cast<uint32_t*>(&h2);
    o4.w = *reinterpret_cast<uint32_t*>(&h3);
    reinterpret_cast<uint4*>(g_Bh + (size_t)o * IN_F)[kw] = o4;
}

// ---------------------------------------------------------------------------
// Main GEMM: mma.sync.m16n8k16 fp16 -> f32, CTA 64x128x64, 3-stage cp.async,
// 3 CTAs per SM. 4 warps in 2(M) x 2(N) grid; warp tile 32x64.
// Smem: K-major 128B rows, SW128 swizzle -> conflict-free ldmatrix.
// ---------------------------------------------------------------------------
__global__ void __launch_bounds__(NTHREADS, 3)
gemm_f16_kernel(const float* __restrict__ bias, float* __restrict__ out) {
    extern __shared__ __align__(1024) char smem[];
    const uint32_t sbase = smem_u32(smem);
    const int tid  = threadIdx.x;
    const int wid  = tid >> 5;
    const int lane = tid & 31;
    const int wm   = wid & 1;        // warp M coord (2)
    const int wn   = wid >> 1;       // warp N coord (2)

    // M-fastest CTA order: concurrent CTAs share B bands; A stays L2-resident.
    const int mt = blockIdx.x & 63;  // 64 M tiles
    const int nt = blockIdx.x >> 6;  // 86 N tiles
    const int m0 = mt * BM;
    const int n0 = nt * BN;

    const __half* Abase = g_Xh + (size_t)m0 * IN_F;
    const __half* Bbase = g_Bh + (size_t)n0 * IN_F;

    // Stage loader: A 512 chunks of 16B (4/thread), B 1024 chunks (8/thread).
    auto load_stage = [&](int s, int kl) {
        const int k0 = kl * BK;
        const uint32_t abuf = sbase + s * STAGE_BYTES;
        const uint32_t bbuf = abuf + A_STAGE_BYTES;
        const __half* Ag = Abase + k0;
        const __half* Bg = Bbase + k0;
        #pragma unroll
        for (int j = 0; j < 4; j++) {
            int q = tid + j * NTHREADS;       // 0..511
            int r = q >> 3;                   // A row 0..63
            int c = q & 7;                    // 16B chunk 0..7
            uint32_t off = (uint32_t)(r * 128 + c * 16);
            uint32_t sw  = off ^ ((off >> 3) & 0x70);
            asm volatile("cp.async.cg.shared.global [%0], [%1], 16;"
                         :: "r"(abuf + sw), "l"(Ag + (size_t)r * IN_F + c * 8)
                         : "memory");
        }
        #pragma unroll
        for (int j = 0; j < 8; j++) {
            int q = tid + j * NTHREADS;       // 0..1023
            int r = q >> 3;                   // B row 0..127
            int c = q & 7;
            uint32_t off = (uint32_t)(r * 128 + c * 16);
            uint32_t sw  = off ^ ((off >> 3) & 0x70);
            asm volatile("cp.async.cg.shared.global [%0], [%1], 16;"
                         :: "r"(bbuf + sw), "l"(Bg + (size_t)r * IN_F + c * 8)
                         : "memory");
        }
    };

    // Prologue: fill NSTAGE-1 stages
    #pragma unroll
    for (int kl = 0; kl < NSTAGE - 1; kl++) {
        load_stage(kl, kl);
        asm volatile("cp.async.commit_group;" ::: "memory");
    }

    float acc[2][8][4];
    #pragma unroll
    for (int mi = 0; mi < 2; mi++)
        #pragma unroll
        for (int nf = 0; nf < 8; nf++)
            #pragma unroll
            for (int e = 0; e < 4; e++) acc[mi][nf][e] = 0.0f;

    const int lrow   = lane & 15;    // ldmatrix source row within 16
    const int lchunk = lane >> 4;    // 0: k0-7 chunk, 1: k8-15 chunk

    for (int kt = 0; kt < NKIT; kt++) {
        asm volatile("cp.async.wait_group %0;" :: "n"(NSTAGE - 2) : "memory");
        __syncthreads();

        // Prefetch stage kt+NSTAGE-1 (its buffer was consumed at kt-1; all
        // warps passed the barrier above, so it is free).
        const int kl = kt + NSTAGE - 1;
        if (kl < NKIT) load_stage(kl % NSTAGE, kl);
        asm volatile("cp.async.commit_group;" ::: "memory");

        // Compute on stage s.
        const int s = kt % NSTAGE;
        const uint32_t abuf = sbase + s * STAGE_BYTES;
        const uint32_t bbuf = abuf + A_STAGE_BYTES;

        #pragma unroll
        for (int k16 = 0; k16 < BK / 16; k16++) {
            uint32_t af[2][4], bf[4][4];
            const int chunk = k16 * 2 + lchunk;
            #pragma unroll
            for (int mi = 0; mi < 2; mi++) {
                int row = wm * 32 + mi * 16 + lrow;
                uint32_t off = (uint32_t)(row * 128 + chunk * 16);
                ldsm_x4(abuf + (off ^ ((off >> 3) & 0x70)), af[mi]);
            }
            #pragma unroll
            for (int nj = 0; nj < 4; nj++) {
                int row = wn * 64 + nj * 16 + lrow;
                uint32_t off = (uint32_t)(row * 128 + chunk * 16);
                ldsm_x4(bbuf + (off ^ ((off >> 3) & 0x70)), bf[nj]);
            }
            #pragma unroll
            for (int mi = 0; mi < 2; mi++)
                #pragma unroll
                for (int nj = 0; nj < 4; nj++) {
                    mma16816(acc[mi][2 * nj],     af[mi], bf[nj][0], bf[nj][2]);
                    mma16816(acc[mi][2 * nj + 1], af[mi], bf[nj][1], bf[nj][3]);
                }
        }
    }

    // Epilogue: fragment layout c0,c1 -> (row=q, col=2c..2c+1), c2,c3 -> row+8.
    const int qrow = lane >> 2;          // 0..7
    const int qcol = (lane & 3) * 2;
    float2 bv[8];
    #pragma unroll
    for (int nf = 0; nf < 8; nf++) {
        int c = n0 + wn * 64 + nf * 8 + qcol;
        bv[nf].x = __ldg(bias + c);
        bv[nf].y = __ldg(bias + c + 1);
    }
    #pragma unroll
    for (int mi = 0; mi < 2; mi++) {
        int gr = m0 + wm * 32 + mi * 16 + qrow;
        float* p0 = out + (size_t)gr * OUT_F;
        float* p1 = p0 + 8 * OUT_F;
        #pragma unroll
        for (int nf = 0; nf < 8; nf++) {
            int c = n0 + wn * 64 + nf * 8 + qcol;
            float2 v0, v1;
            v0.x = acc[mi][nf][0] + bv[nf].x;
            v0.y = acc[mi][nf][1] + bv[nf].y;
            v1.x = acc[mi][nf][2] + bv[nf].x;
            v1.y = acc[mi][nf][3] + bv[nf].y;
            *reinterpret_cast<float2*>(p0 + c) = v0;
            *reinterpret_cast<float2*>(p1 + c) = v1;
        }
    }
}

// ---------------------------------------------------------------------------
extern "C" void kernel_launch(void* const* d_in, const int* in_sizes, int n_in,
                              void* d_out, int out_size) {
    const float*    x    = (const float*)   d_in[0];
    const uint32_t* qw   = (const uint32_t*)d_in[1];
    const uint32_t* qz   = (const uint32_t*)d_in[2];
    const float*    sc   = (const float*)   d_in[3];
    const float*    bias = (const float*)   d_in[4];
    float*          out  = (float*)d_out;

    // 1) x -> fp16
    {
        int n8 = TOKENS * IN_F / 8;
        conv_x_kernel<<<(n8 + 255) / 256, 256>>>((const float4*)x, n8);
    }
    // 2) dequantize weights -> fp16 (once, hoisted out of the GEMM mainloop)
    {
        int n = OUT_F * KWORDS;
        dequant_kernel<<<(n + 255) / 256, 256>>>(qw, qz, sc);
    }
    // 3) fp16 mma.sync GEMM, 3 CTAs/SM, 64x128 tiles
    cudaFuncSetAttribute(gemm_f16_kernel,
                         cudaFuncAttributeMaxDynamicSharedMemorySize, SMEM_TOTAL);
    dim3 grid((TOKENS / BM) * (OUT_F / BN));  // 64 * 86 = 5504, M-fastest
    gemm_f16_kernel<<<grid, NTHREADS, SMEM_TOTAL>>>(bias, out);
}